// round 1
// baseline (speedup 1.0000x reference)
#include <cuda_runtime.h>
#include <math.h>

// Problem constants
#define NB 4
#define HH 64
#define WW 64
#define HW 4096
#define CIN 256
#define DC 64
#define COUT 256
#define KK 9

// Scratch: max K for im2col is 320*9=2880 rows (stage 1). 4 batches.
__device__ float g_cols[(size_t)NB * 2880 * HW];       // ~189 MB
__device__ float g_offsets[(size_t)NB * 18 * HW];      // offset conv output
__device__ float g_mask[(size_t)NB * 9 * HW];          // sigmoid mask

// ---------------------------------------------------------------------------
// Regular im2col of cat(x, depth): cols[n][(c*9+k)][p]
// grid: (HW/256, 320, NB), block 256
// ---------------------------------------------------------------------------
__global__ void im2col_cat_kernel(const float* __restrict__ x,
                                  const float* __restrict__ depth,
                                  float* __restrict__ cols) {
    int p = blockIdx.x * blockDim.x + threadIdx.x;   // 0..4095
    int c = blockIdx.y;                              // 0..319
    int n = blockIdx.z;
    const float* src = (c < CIN)
        ? x     + ((size_t)n * CIN + c) * HW
        : depth + ((size_t)n * DC + (c - CIN)) * HW;
    int h = p >> 6, w = p & 63;
    float* dst = cols + ((size_t)n * 2880 + (size_t)c * 9) * HW + p;
#pragma unroll
    for (int kh = 0; kh < 3; kh++) {
#pragma unroll
        for (int kw = 0; kw < 3; kw++) {
            int iy = h + kh - 1, ix = w + kw - 1;
            float v = (iy >= 0 && iy < HH && ix >= 0 && ix < WW)
                          ? src[iy * WW + ix] : 0.f;
            dst[(size_t)(kh * 3 + kw) * HW] = v;
        }
    }
}

// ---------------------------------------------------------------------------
// Deformable im2col: cols[n][(c*9+k)][p] with bilinear sampling.
// offsets layout [n][k*2 + {0:dy,1:dx}][p] (DG=1). Optional mask [n][k][p].
// grid: (HW/256, C, NB)
// ---------------------------------------------------------------------------
template <bool HASMASK>
__global__ void deform_im2col_kernel(const float* __restrict__ xin, int C,
                                     const float* __restrict__ offs,
                                     const float* __restrict__ mask,
                                     float* __restrict__ cols) {
    int p = blockIdx.x * blockDim.x + threadIdx.x;
    int c = blockIdx.y;
    int n = blockIdx.z;
    int h = p >> 6, w = p & 63;
    const float* src = xin + ((size_t)n * C + c) * HW;
    const float* offn = offs + (size_t)n * 18 * HW;
    const float* maskn = HASMASK ? (mask + (size_t)n * 9 * HW) : nullptr;
    float* dst = cols + ((size_t)n * C * 9 + (size_t)c * 9) * HW + p;
#pragma unroll
    for (int k = 0; k < 9; k++) {
        int kh = k / 3, kw = k % 3;
        float dy = offn[(size_t)(2 * k + 0) * HW + p];
        float dx = offn[(size_t)(2 * k + 1) * HW + p];
        float y  = (float)(h - 1 + kh) + dy;
        float xx = (float)(w - 1 + kw) + dx;
        float y0f = floorf(y), x0f = floorf(xx);
        float ly = y - y0f, lx = xx - x0f;
        int y0 = (int)y0f, x0 = (int)x0f;
        int y1 = y0 + 1, x1 = x0 + 1;
        bool vy0 = (y0 >= 0) & (y0 < HH);
        bool vy1 = (y1 >= 0) & (y1 < HH);
        bool vx0 = (x0 >= 0) & (x0 < WW);
        bool vx1 = (x1 >= 0) & (x1 < WW);
        float v00 = (vy0 & vx0) ? src[y0 * WW + x0] : 0.f;
        float v01 = (vy0 & vx1) ? src[y0 * WW + x1] : 0.f;
        float v10 = (vy1 & vx0) ? src[y1 * WW + x0] : 0.f;
        float v11 = (vy1 & vx1) ? src[y1 * WW + x1] : 0.f;
        float v = v00 * (1.f - ly) * (1.f - lx)
                + v01 * (1.f - ly) * lx
                + v10 * ly * (1.f - lx)
                + v11 * ly * lx;
        if (HASMASK) v *= maskn[(size_t)k * HW + p];
        dst[(size_t)k * HW] = v;
    }
}

// ---------------------------------------------------------------------------
// Tiled SGEMM: C[n][M][4096] = A[M][K] * B[n][K][4096] + bias (opt sigmoid)
// Register-prefetched single smem buffer. 256 threads.
// grid: (4096/BN, ceil(M/BM), NB)
// ---------------------------------------------------------------------------
template <int BM, int BN, int BK, int TM, int TN, bool SIG>
__global__ void __launch_bounds__(256, 2)
sgemm_kernel(const float* __restrict__ A, const float* __restrict__ B,
             const float* __restrict__ bias, float* __restrict__ C,
             int M, int K) {
    constexpr int NT = 256;
    constexpr int BMP = BM + 4;                 // pad to soften STS conflicts
    __shared__ float As[BK][BMP];
    __shared__ float Bs[BK][BN];
    constexpr int numA4 = BM * BK / 4;
    constexpr int numB4 = BK * BN / 4;
    constexpr int AI = (numA4 + NT - 1) / NT;
    constexpr int BI = (numB4 + NT - 1) / NT;

    const int tid = threadIdx.x;
    const int n0 = blockIdx.x * BN;
    const int m0 = blockIdx.y * BM;
    const int batch = blockIdx.z;
    const float* Bb = B + (size_t)batch * K * HW;
    float* Cb = C + (size_t)batch * M * HW;

    const int tx = tid % (BN / TN);
    const int ty = tid / (BN / TN);

    float acc[TM][TN];
#pragma unroll
    for (int i = 0; i < TM; i++)
#pragma unroll
        for (int j = 0; j < TN; j++) acc[i][j] = 0.f;

    float4 ra[AI], rb[BI];

    auto loadA = [&](int k0) {
#pragma unroll
        for (int t = 0; t < AI; t++) {
            int idx = tid + t * NT;
            if (AI * NT == numA4 || idx < numA4) {
                int row = idx / (BK / 4);
                int kq = idx % (BK / 4);
                int gm = m0 + row;
                if (gm < M)
                    ra[t] = *reinterpret_cast<const float4*>(
                        &A[(size_t)gm * K + k0 + kq * 4]);
                else
                    ra[t] = make_float4(0.f, 0.f, 0.f, 0.f);
            }
        }
    };
    auto loadB = [&](int k0) {
#pragma unroll
        for (int t = 0; t < BI; t++) {
            int idx = tid + t * NT;
            int row = idx / (BN / 4);
            int c4 = idx % (BN / 4);
            rb[t] = *reinterpret_cast<const float4*>(
                &Bb[(size_t)(k0 + row) * HW + n0 + c4 * 4]);
        }
    };
    auto storeA = [&]() {
#pragma unroll
        for (int t = 0; t < AI; t++) {
            int idx = tid + t * NT;
            if (AI * NT == numA4 || idx < numA4) {
                int row = idx / (BK / 4);
                int kq = idx % (BK / 4);
                As[kq * 4 + 0][row] = ra[t].x;
                As[kq * 4 + 1][row] = ra[t].y;
                As[kq * 4 + 2][row] = ra[t].z;
                As[kq * 4 + 3][row] = ra[t].w;
            }
        }
    };
    auto storeB = [&]() {
#pragma unroll
        for (int t = 0; t < BI; t++) {
            int idx = tid + t * NT;
            int row = idx / (BN / 4);
            int c4 = idx % (BN / 4);
            *reinterpret_cast<float4*>(&Bs[row][c4 * 4]) = rb[t];
        }
    };

    loadA(0); loadB(0);
    storeA(); storeB();
    __syncthreads();

    const int ktiles = K / BK;
    for (int t = 0; t < ktiles; t++) {
        if (t + 1 < ktiles) { loadA((t + 1) * BK); loadB((t + 1) * BK); }
#pragma unroll
        for (int kk = 0; kk < BK; kk++) {
            float a[TM], b[TN];
#pragma unroll
            for (int i = 0; i < TM; i++) a[i] = As[kk][ty * TM + i];
#pragma unroll
            for (int j = 0; j < TN; j++) b[j] = Bs[kk][tx * TN + j];
#pragma unroll
            for (int i = 0; i < TM; i++)
#pragma unroll
                for (int j = 0; j < TN; j++) acc[i][j] += a[i] * b[j];
        }
        __syncthreads();
        if (t + 1 < ktiles) { storeA(); storeB(); __syncthreads(); }
    }

    // Epilogue: bias (+ sigmoid), vectorized store
#pragma unroll
    for (int i = 0; i < TM; i++) {
        int gm = m0 + ty * TM + i;
        if (gm < M) {
            float bi = bias[gm];
            float vals[TN];
#pragma unroll
            for (int j = 0; j < TN; j++) {
                float v = acc[i][j] + bi;
                if (SIG) v = 1.f / (1.f + expf(-v));
                vals[j] = v;
            }
            float* cp = &Cb[(size_t)gm * HW + n0 + tx * TN];
#pragma unroll
            for (int j = 0; j < TN; j += 4) {
                *reinterpret_cast<float4*>(cp + j) =
                    make_float4(vals[j], vals[j + 1], vals[j + 2], vals[j + 3]);
            }
        }
    }
}

// ---------------------------------------------------------------------------
extern "C" void kernel_launch(void* const* d_in, const int* in_sizes, int n_in,
                              void* d_out, int out_size) {
    const float* x      = (const float*)d_in[0];
    const float* depth  = (const float*)d_in[1];
    const float* weight = (const float*)d_in[2];
    const float* bias   = (const float*)d_in[3];
    const float* off_w  = (const float*)d_in[4];
    const float* off_b  = (const float*)d_in[5];
    const float* mask_w = (const float*)d_in[6];
    const float* mask_b = (const float*)d_in[7];
    float* out = (float*)d_out;

    void *pc, *po, *pm;
    cudaGetSymbolAddress(&pc, g_cols);
    cudaGetSymbolAddress(&po, g_offsets);
    cudaGetSymbolAddress(&pm, g_mask);
    float* cols = (float*)pc;
    float* offsets = (float*)po;
    float* maskbuf = (float*)pm;

    // Stage 1: offset = conv3x3(cat(x, depth), off_w) + off_b
    im2col_cat_kernel<<<dim3(HW / 256, 320, NB), 256>>>(x, depth, cols);
    sgemm_kernel<32, 128, 16, 2, 8, false>
        <<<dim3(HW / 128, 1, NB), 256>>>(off_w, cols, off_b, offsets, 18, 2880);

    // Stage 2: mask = sigmoid(deform_conv(depth, offset, mask_w) + mask_b)
    deform_im2col_kernel<false>
        <<<dim3(HW / 256, DC, NB), 256>>>(depth, DC, offsets, nullptr, cols);
    sgemm_kernel<32, 128, 16, 2, 8, true>
        <<<dim3(HW / 128, 1, NB), 256>>>(mask_w, cols, mask_b, maskbuf, 9, 576);

    // Stage 3: out = mod_deform_conv(x, offset, mask, weight) + bias
    deform_im2col_kernel<true>
        <<<dim3(HW / 256, CIN, NB), 256>>>(x, CIN, offsets, maskbuf, cols);
    sgemm_kernel<128, 64, 16, 8, 4, false>
        <<<dim3(HW / 64, COUT / 128, NB), 256>>>(weight, cols, bias, out,
                                                 COUT, 2304);
}